// round 7
// baseline (speedup 1.0000x reference)
#include <cuda_runtime.h>
#include <cstdint>

#define G_   200
#define NPG  500
#define EPG  6000
#define ETOT (G_*EPG)
#define F_   64
#define KPG  250
#define NTH  512
#define NW   (NTH/32)

struct __align__(16) SmemLayout {
    float           arena[NPG * 32];            // xhalf(P1) / u64 sort buf(P2) / HB(P3+)
    union {                                     // 24832B
        struct {
            float W1s[F_][F_];                  // 16384B (P3+)
            float b1s[F_];
            float zst[NW][2][F_];               // 8192B
        } mm;
        unsigned pe[EPG];                       // packed (r<<16|c) edges (P0)
        float    ew[EPG];                       // per-edge weights dis_s*dis_d (P1)
    } u2;
    unsigned short  csr_src[EPG];               // 12000B; overlaid by rsum/rmax at readout
    unsigned        col_off[NPG + 4];
    float           dis[NPG];
    float           scorev[NTH];                // icnt(P0) -> scores(P1) -> logit_s(P4)
    int             sidx[NTH];                  // outdeg(P0)
    int             wsum[32];
    unsigned short  klist[KPG + 2];
    short           mapv[NPG];
    float           d2k[KPG];
    float           ninv[KPG];
    unsigned short  vcnt[KPG + 2];
};

__device__ __forceinline__ float warp_sum(float v) {
    #pragma unroll
    for (int o = 16; o; o >>= 1) v += __shfl_xor_sync(0xffffffffu, v, o);
    return v;
}
__device__ __forceinline__ unsigned long long shfl_xor_u64(unsigned long long v, int m) {
    unsigned lo = (unsigned)v, hi = (unsigned)(v >> 32);
    lo = __shfl_xor_sync(0xffffffffu, lo, m);
    hi = __shfl_xor_sync(0xffffffffu, hi, m);
    return ((unsigned long long)hi << 32) | lo;
}

__global__ __launch_bounds__(NTH, 2)
void gp_fused_kernel(const float* __restrict__ x,
                     const int*   __restrict__ ei,
                     const float* __restrict__ W1,
                     const float* __restrict__ b1,
                     const float* __restrict__ beta_p,
                     float*       __restrict__ out)
{
    extern __shared__ __align__(16) unsigned char smraw[];
    SmemLayout& S = *reinterpret_cast<SmemLayout*>(smraw);

    const int g    = blockIdx.x;
    const int tid  = threadIdx.x;
    const int wid  = tid >> 5;
    const int lane = tid & 31;
    const int base = g * NPG;
    const int* __restrict__ erow = ei + (size_t)g * EPG;
    const int* __restrict__ ecol = ei + (size_t)ETOT + (size_t)g * EPG;
    const float* __restrict__ xg = x + (size_t)base * F_;

    // ===== Phase 0: degrees + packed-edge cache + CSR + edge weights ========
    int* icnt = reinterpret_cast<int*>(S.scorev);
    icnt[tid]   = 0;
    S.sidx[tid] = 0;
    __syncthreads();

    for (int e = tid; e < EPG; e += NTH) {          // single global edge sweep
        int r = erow[e] - base;
        int c = ecol[e] - base;
        S.u2.pe[e] = ((unsigned)r << 16) | (unsigned)c;
        atomicAdd(&S.sidx[r], 1);
        atomicAdd(&icnt[c],  1);
    }
    __syncthreads();

    for (int n = tid; n < NPG; n += NTH) {
        int d = S.sidx[n];
        S.dis[n] = (d > 0) ? (1.0f / sqrtf((float)d)) : 0.0f;
    }
    {   // hierarchical exclusive scan of icnt -> col_off starts
        int v = icnt[tid];
        int inc = v;
        #pragma unroll
        for (int o = 1; o < 32; o <<= 1) {
            int u = __shfl_up_sync(0xffffffffu, inc, o);
            if (lane >= o) inc += u;
        }
        if (lane == 31) S.wsum[wid] = inc;
        __syncthreads();
        if (tid < 16) {
            int s = S.wsum[tid];
            #pragma unroll
            for (int o = 1; o < 16; o <<= 1) {
                int u = __shfl_up_sync(0x0000ffffu, s, o);
                if (tid >= o) s += u;
            }
            S.wsum[tid] = s;
        }
        __syncthreads();
        int pre = (wid > 0) ? S.wsum[wid - 1] : 0;
        if (tid < NPG + 1) S.col_off[tid] = (unsigned)(inc - v + pre);
    }
    __syncthreads();

    for (int e = tid; e < EPG; e += NTH) {          // scatter from SMEM cache
        unsigned p = S.u2.pe[e];
        int r = (int)(p >> 16);
        int c = (int)(p & 0xffffu);
        unsigned pos = atomicAdd(&S.col_off[c], 1u);
        S.csr_src[pos] = (unsigned short)r;
    }
    __syncthreads();
    // segment(n) = [ n? col_off[n-1]:0 , col_off[n] )

    // edge weights ew[k] = dis[src]*dis[dst], CSR order (overwrites pe)
    if (tid < NPG) {
        unsigned kb = tid ? S.col_off[tid - 1] : 0u;
        unsigned ke = S.col_off[tid];
        float dn = S.dis[tid];
        for (unsigned k = kb; k < ke; ++k)
            S.u2.ew[k] = S.dis[S.csr_src[k]] * dn;
    }
    __syncthreads();

    // ================= Phase 1: score, two 32-feature passes, ILP-4 ========
    #pragma unroll
    for (int pass = 0; pass < 2; ++pass) {
        for (int i = tid; i < NPG * 32; i += NTH) {
            int n = i >> 5, f = i & 31;
            S.arena[i] = xg[n * F_ + pass * 32 + f];
        }
        __syncthreads();
        for (int n = wid; n < NPG; n += NW) {
            float xc = S.arena[n * 32 + lane];
            unsigned kb = n ? S.col_off[n - 1] : 0u;
            unsigned ke = S.col_off[n];
            float a0 = 0.f, a1 = 0.f, a2 = 0.f, a3 = 0.f;
            unsigned k = kb;
            for (; k + 4 <= ke; k += 4) {
                int s0 = S.csr_src[k + 0], s1 = S.csr_src[k + 1];
                int s2 = S.csr_src[k + 2], s3 = S.csr_src[k + 3];
                a0 = fmaf(S.u2.ew[k + 0], S.arena[s0 * 32 + lane], a0);
                a1 = fmaf(S.u2.ew[k + 1], S.arena[s1 * 32 + lane], a1);
                a2 = fmaf(S.u2.ew[k + 2], S.arena[s2 * 32 + lane], a2);
                a3 = fmaf(S.u2.ew[k + 3], S.arena[s3 * 32 + lane], a3);
            }
            for (; k < ke; ++k) {
                int s = S.csr_src[k];
                a0 = fmaf(S.u2.ew[k], S.arena[s * 32 + lane], a0);
            }
            float a = (a0 + a1) + (a2 + a3);
            float v = warp_sum(fabsf(xc - a));
            if (lane == 0) {
                if (pass == 0) S.scorev[n] = v;
                else           S.scorev[n] += v;
            }
        }
        __syncthreads();
    }

    // ====== Phase 2: hybrid bitonic sort on packed u64 (score desc, idx asc)
    unsigned long long key;
    {
        float sc = (tid < NPG) ? S.scorev[tid] : -3.4e38f;
        unsigned sb  = __float_as_uint(sc);
        unsigned ord = (sb & 0x80000000u) ? ~sb : (sb | 0x80000000u);
        key = ((unsigned long long)ord << 32) | (unsigned)(~tid);
    }
    unsigned long long* kb64 = reinterpret_cast<unsigned long long*>(S.arena);
    __syncthreads();                            // arena reads (P1) done

    #pragma unroll
    for (int k = 2; k <= 32; k <<= 1) {         // k = 2..32 in registers
        #pragma unroll
        for (int j = k >> 1; j > 0; j >>= 1) {
            unsigned long long pk = shfl_xor_u64(key, j);
            bool isLow   = ((lane & j) == 0);
            bool dirDesc = ((tid  & k) == 0);
            bool takeMax = (isLow == dirDesc);
            key = ((pk > key) == takeMax) ? pk : key;
        }
    }
    #pragma unroll
    for (int k = 64; k <= NTH; k <<= 1) {       // k = 64..512
        for (int j = k >> 1; j >= 32; j >>= 1) {
            kb64[tid] = key;
            __syncthreads();
            unsigned long long pk = kb64[tid ^ j];
            bool isLow   = ((tid & j) == 0);
            bool dirDesc = ((tid & k) == 0);
            bool takeMax = (isLow == dirDesc);
            key = ((pk > key) == takeMax) ? pk : key;
            __syncthreads();
        }
        #pragma unroll
        for (int j = 16; j > 0; j >>= 1) {
            unsigned long long pk = shfl_xor_u64(key, j);
            bool isLow   = ((lane & j) == 0);
            bool dirDesc = ((tid  & k) == 0);
            bool takeMax = (isLow == dirDesc);
            key = ((pk > key) == takeMax) ? pk : key;
        }
    }
    for (int n = tid; n < NPG; n += NTH) S.mapv[n] = -1;
    __syncthreads();
    if (tid < KPG) {
        int idx = (int)(~(unsigned)key) & (NTH - 1);
        S.klist[tid] = (unsigned short)idx;
        S.mapv[idx]  = (short)tid;
    }
    __syncthreads();

    // ====== Phase 3a: W1/b1 stage, in-place CSR compaction, d2 ==============
    {
        const float4* src = reinterpret_cast<const float4*>(W1);
        float4*       dst = reinterpret_cast<float4*>(&S.u2.mm.W1s[0][0]);
        for (int i = tid; i < F_ * F_ / 4; i += NTH) dst[i] = src[i];
    }
    if (tid < F_) S.u2.mm.b1s[tid] = b1[tid];
    const float beta = beta_p[0];

    if (tid < KPG) {
        int n = S.klist[tid];
        unsigned kb = n ? S.col_off[n - 1] : 0u;
        unsigned ke = S.col_off[n];
        unsigned w  = kb;
        for (unsigned k = kb; k < ke; ++k) {
            short m = S.mapv[S.csr_src[k]];
            if (m >= 0) S.csr_src[w++] = (unsigned short)m;
        }
        int cnt = (int)(w - kb);
        S.vcnt[tid] = (unsigned short)cnt;
        S.d2k[tid]  = 1.0f / sqrtf((float)(cnt + 1));
    }
    __syncthreads();

    // ====== Phase 3b: z-gather (global) + matmul, HB = relu(zW1+b) ==========
    float2* HB2 = reinterpret_cast<float2*>(S.arena);
    const float2* W2 = reinterpret_cast<const float2*>(&S.u2.mm.W1s[0][0]);
    {
        float2 b2 = reinterpret_cast<const float2*>(S.u2.mm.b1s)[lane];
        for (int i0 = 2 * wid; i0 < KPG; i0 += 2 * NW) {
            #pragma unroll
            for (int r = 0; r < 2; ++r) {
                int i = i0 + r;
                if (i >= KPG) break;
                int n = S.klist[i];
                float d2c = S.d2k[i];
                const float2* xr = reinterpret_cast<const float2*>(xg + (size_t)n * F_);
                float2 xv = xr[lane];
                float  sf = d2c * d2c;
                float2 z  = make_float2(sf * xv.x, sf * xv.y);
                unsigned kb = n ? S.col_off[n - 1] : 0u;
                unsigned ke = kb + S.vcnt[i];
                for (unsigned k = kb; k < ke; ++k) {
                    int rs = S.csr_src[k];
                    float nm = S.d2k[rs] * d2c;
                    const float2* xj = reinterpret_cast<const float2*>(
                        xg + (size_t)S.klist[rs] * F_);
                    float2 xw = xj[lane];
                    z.x = fmaf(nm, xw.x, z.x);
                    z.y = fmaf(nm, xw.y, z.y);
                }
                reinterpret_cast<float2*>(S.u2.mm.zst[wid][r])[lane] = z;
            }
            __syncwarp();
            float2 a0 = b2, a1 = b2;
            #pragma unroll
            for (int k2 = 0; k2 < F_; ++k2) {
                float2 w = W2[k2 * 32 + lane];
                float z0 = S.u2.mm.zst[wid][0][k2];
                float z1 = S.u2.mm.zst[wid][1][k2];
                a0.x = fmaf(z0, w.x, a0.x);  a0.y = fmaf(z0, w.y, a0.y);
                a1.x = fmaf(z1, w.x, a1.x);  a1.y = fmaf(z1, w.y, a1.y);
            }
            HB2[i0 * 32 + lane] = make_float2(fmaxf(a0.x, 0.f), fmaxf(a0.y, 0.f));
            if (i0 + 1 < KPG)
                HB2[(i0 + 1) * 32 + lane] = make_float2(fmaxf(a1.x, 0.f), fmaxf(a1.y, 0.f));
            __syncwarp();
        }
    }
    __syncthreads();

    // ================= Phase 4a: norms + self logits ========================
    for (int i = wid; i < KPG; i += NW) {
        float2 h = HB2[i * 32 + lane];
        float ss = warp_sum(h.x * h.x + h.y * h.y);
        float ni = 1.0f / fmaxf(sqrtf(ss), 1e-12f);
        if (lane == 0) {
            S.ninv[i]   = ni;
            S.scorev[i] = beta * ss * ni * ni;      // logit_s
        }
    }
    __syncthreads();

    // ====== Phase 4b: AGNN chunk-4 online softmax + fused readout ===========
    float2 msum = make_float2(0.f, 0.f);
    float2 mmax = make_float2(-3.4e38f, -3.4e38f);
    for (int i = wid; i < KPG; i += NW) {
        int n = S.klist[i];
        unsigned kb = n ? S.col_off[n - 1] : 0u;
        int dv = (int)S.vcnt[i];
        float ni = S.ninv[i];
        float2 hn = HB2[i * 32 + lane];
        float m     = S.scorev[i];                  // logit_s
        float denom = 1.0f;
        float2 acc  = hn;
        for (int c = 0; c < dv; c += 4) {
            int cnt = dv - c;  if (cnt > 4) cnt = 4;
            int   rs0, rs1, rs2, rs3;
            float d0, d1, d2, d3;
            rs0 = S.csr_src[kb + c];
            rs1 = (cnt > 1) ? (int)S.csr_src[kb + c + 1] : rs0;
            rs2 = (cnt > 2) ? (int)S.csr_src[kb + c + 2] : rs0;
            rs3 = (cnt > 3) ? (int)S.csr_src[kb + c + 3] : rs0;
            {
                float2 h0 = HB2[rs0 * 32 + lane];
                float2 h1 = HB2[rs1 * 32 + lane];
                float2 h2 = HB2[rs2 * 32 + lane];
                float2 h3 = HB2[rs3 * 32 + lane];
                d0 = fmaf(hn.x, h0.x, hn.y * h0.y);
                d1 = fmaf(hn.x, h1.x, hn.y * h1.y);
                d2 = fmaf(hn.x, h2.x, hn.y * h2.y);
                d3 = fmaf(hn.x, h3.x, hn.y * h3.y);
            }
            #pragma unroll
            for (int o = 16; o; o >>= 1) {          // 4 interleaved trees
                d0 += __shfl_xor_sync(0xffffffffu, d0, o);
                d1 += __shfl_xor_sync(0xffffffffu, d1, o);
                d2 += __shfl_xor_sync(0xffffffffu, d2, o);
                d3 += __shfl_xor_sync(0xffffffffu, d3, o);
            }
            d0 = beta * d0 * ni * S.ninv[rs0];
            d1 = (cnt > 1) ? beta * d1 * ni * S.ninv[rs1] : -3.4e38f;
            d2 = (cnt > 2) ? beta * d2 * ni * S.ninv[rs2] : -3.4e38f;
            d3 = (cnt > 3) ? beta * d3 * ni * S.ninv[rs3] : -3.4e38f;
            float cm = fmaxf(fmaxf(d0, d1), fmaxf(d2, d3));
            float mn = fmaxf(m, cm);
            float cr = __expf(m - mn);
            denom *= cr;
            acc.x *= cr;  acc.y *= cr;
            {
                float e0 = __expf(d0 - mn);
                float2 hs = HB2[rs0 * 32 + lane];
                denom += e0;
                acc.x = fmaf(e0, hs.x, acc.x);
                acc.y = fmaf(e0, hs.y, acc.y);
            }
            if (cnt > 1) {
                float e1 = __expf(d1 - mn);
                float2 hs = HB2[rs1 * 32 + lane];
                denom += e1;
                acc.x = fmaf(e1, hs.x, acc.x);
                acc.y = fmaf(e1, hs.y, acc.y);
            }
            if (cnt > 2) {
                float e2 = __expf(d2 - mn);
                float2 hs = HB2[rs2 * 32 + lane];
                denom += e2;
                acc.x = fmaf(e2, hs.x, acc.x);
                acc.y = fmaf(e2, hs.y, acc.y);
            }
            if (cnt > 3) {
                float e3 = __expf(d3 - mn);
                float2 hs = HB2[rs3 * 32 + lane];
                denom += e3;
                acc.x = fmaf(e3, hs.x, acc.x);
                acc.y = fmaf(e3, hs.y, acc.y);
            }
            m = mn;
        }
        float inv = 1.0f / denom;
        float2 o = make_float2(acc.x * inv, acc.y * inv);
        msum.x += o.x;  msum.y += o.y;
        mmax.x = fmaxf(mmax.x, o.x);
        mmax.y = fmaxf(mmax.y, o.y);
    }
    __syncthreads();                                 // csr_src now dead
    {
        float* RS = reinterpret_cast<float*>(S.csr_src);        // [16][64]
        float* RM = RS + NW * F_;                               // [16][64]
        reinterpret_cast<float2*>(RS)[wid * 32 + lane] = msum;
        reinterpret_cast<float2*>(RM)[wid * 32 + lane] = mmax;
        __syncthreads();
        if (tid < F_) {
            float s = 0.f;
            #pragma unroll
            for (int w = 0; w < NW; ++w) s += RS[w * F_ + tid];
            out[(size_t)g * (2 * F_) + tid] = fmaxf(s * (1.0f / (float)KPG), 0.f);
        } else if (tid < 2 * F_) {
            int f = tid - F_;
            float m2 = -3.4e38f;
            #pragma unroll
            for (int w = 0; w < NW; ++w) m2 = fmaxf(m2, RM[w * F_ + f]);
            out[(size_t)g * (2 * F_) + F_ + f] = fmaxf(m2, 0.f);
        }
    }
}

extern "C" void kernel_launch(void* const* d_in, const int* in_sizes, int n_in,
                              void* d_out, int out_size)
{
    const float* x    = (const float*)d_in[0];
    const int*   ei   = (const int*)  d_in[1];
    const float* W1   = (const float*)d_in[2];
    const float* b1   = (const float*)d_in[3];
    const float* beta = (const float*)d_in[4];
    float*       out  = (float*)d_out;

    int smem = (int)sizeof(SmemLayout);
    cudaFuncSetAttribute(gp_fused_kernel,
                         cudaFuncAttributeMaxDynamicSharedMemorySize, smem);
    gp_fused_kernel<<<G_, NTH, smem>>>(x, ei, W1, b1, beta, out);
}

// round 10
// speedup vs baseline: 1.1836x; 1.1836x over previous
#include <cuda_runtime.h>
#include <cstdint>

#define G_   200
#define NPG  500
#define EPG  6000
#define ETOT (G_*EPG)
#define F_   64
#define KPG  250
#define NTH  512
#define NW   (NTH/32)

struct __align__(16) SmemLayout {
    float           arena[NPG * 32];            // u64 sort buf(P2) / HB(P3+)
    union {                                     // 24832B
        struct {
            float W1s[F_][F_];                  // 16384B (P3+)
            float b1s[F_];
            float zst[NW][2][F_];               // 8192B
        } mm;
        unsigned pe[EPG];                       // packed (r<<16|c) edges (P0)
    } u2;
    unsigned short  csr_src[EPG];               // 12000B; overlaid by rsum/rmax at readout
    unsigned        col_off[NPG + 4];
    float           dis[NPG];
    float           scorev[NTH];                // icnt(P0) -> scores(P1) -> logit_s(P3b+)
    int             sidx[NTH];                  // outdeg(P0)
    int             wsum[32];
    unsigned short  klist[KPG + 2];
    short           mapv[NPG];
    float           d2k[KPG];
    float           ninv[KPG];
    unsigned short  vcnt[KPG + 2];
};

__device__ __forceinline__ float warp_sum(float v) {
    #pragma unroll
    for (int o = 16; o; o >>= 1) v += __shfl_xor_sync(0xffffffffu, v, o);
    return v;
}
__device__ __forceinline__ unsigned long long shfl_xor_u64(unsigned long long v, int m) {
    unsigned lo = (unsigned)v, hi = (unsigned)(v >> 32);
    lo = __shfl_xor_sync(0xffffffffu, lo, m);
    hi = __shfl_xor_sync(0xffffffffu, hi, m);
    return ((unsigned long long)hi << 32) | lo;
}

__global__ __launch_bounds__(NTH, 2)
void gp_fused_kernel(const float* __restrict__ x,
                     const int*   __restrict__ ei,
                     const float* __restrict__ W1,
                     const float* __restrict__ b1,
                     const float* __restrict__ beta_p,
                     float*       __restrict__ out)
{
    extern __shared__ __align__(16) unsigned char smraw[];
    SmemLayout& S = *reinterpret_cast<SmemLayout*>(smraw);

    const int g    = blockIdx.x;
    const int tid  = threadIdx.x;
    const int wid  = tid >> 5;
    const int lane = tid & 31;
    const int base = g * NPG;
    const int* __restrict__ erow = ei + (size_t)g * EPG;
    const int* __restrict__ ecol = ei + (size_t)ETOT + (size_t)g * EPG;
    const float* __restrict__ xg = x + (size_t)base * F_;

    // ===== Phase 0: degrees + packed-edge cache + CSR ========================
    int* icnt = reinterpret_cast<int*>(S.scorev);
    icnt[tid]   = 0;
    S.sidx[tid] = 0;
    __syncthreads();

    for (int e = tid; e < EPG; e += NTH) {          // single global edge sweep
        int r = erow[e] - base;
        int c = ecol[e] - base;
        S.u2.pe[e] = ((unsigned)r << 16) | (unsigned)c;
        atomicAdd(&S.sidx[r], 1);
        atomicAdd(&icnt[c],  1);
    }
    __syncthreads();

    for (int n = tid; n < NPG; n += NTH) {
        int d = S.sidx[n];
        S.dis[n] = (d > 0) ? (1.0f / sqrtf((float)d)) : 0.0f;
    }
    {   // hierarchical exclusive scan of icnt -> col_off starts
        int v = icnt[tid];
        int inc = v;
        #pragma unroll
        for (int o = 1; o < 32; o <<= 1) {
            int u = __shfl_up_sync(0xffffffffu, inc, o);
            if (lane >= o) inc += u;
        }
        if (lane == 31) S.wsum[wid] = inc;
        __syncthreads();
        if (tid < 16) {
            int s = S.wsum[tid];
            #pragma unroll
            for (int o = 1; o < 16; o <<= 1) {
                int u = __shfl_up_sync(0x0000ffffu, s, o);
                if (tid >= o) s += u;
            }
            S.wsum[tid] = s;
        }
        __syncthreads();
        int pre = (wid > 0) ? S.wsum[wid - 1] : 0;
        if (tid < NPG + 1) S.col_off[tid] = (unsigned)(inc - v + pre);
    }
    __syncthreads();

    for (int e = tid; e < EPG; e += NTH) {          // scatter from SMEM cache
        unsigned p = S.u2.pe[e];
        int r = (int)(p >> 16);
        int c = (int)(p & 0xffffu);
        unsigned pos = atomicAdd(&S.col_off[c], 1u);
        S.csr_src[pos] = (unsigned short)r;
    }
    __syncthreads();
    // segment(n) = [ n? col_off[n-1]:0 , col_off[n] )

    // ===== Phase 1: score, single pass from global (lane = float2) ==========
    for (int n = wid; n < NPG; n += NW) {
        const float2* xr = reinterpret_cast<const float2*>(xg + (size_t)n * F_);
        float2 xc = xr[lane];
        float  dn = S.dis[n];
        unsigned kb = n ? S.col_off[n - 1] : 0u;
        unsigned ke = S.col_off[n];
        float2 a0 = make_float2(0.f, 0.f), a1 = make_float2(0.f, 0.f);
        float2 a2 = make_float2(0.f, 0.f), a3 = make_float2(0.f, 0.f);
        unsigned k = kb;
        for (; k + 4 <= ke; k += 4) {
            int s0 = S.csr_src[k + 0], s1 = S.csr_src[k + 1];
            int s2 = S.csr_src[k + 2], s3 = S.csr_src[k + 3];
            float2 v0 = reinterpret_cast<const float2*>(xg + (size_t)s0 * F_)[lane];
            float2 v1 = reinterpret_cast<const float2*>(xg + (size_t)s1 * F_)[lane];
            float2 v2 = reinterpret_cast<const float2*>(xg + (size_t)s2 * F_)[lane];
            float2 v3 = reinterpret_cast<const float2*>(xg + (size_t)s3 * F_)[lane];
            float w0 = S.dis[s0] * dn, w1 = S.dis[s1] * dn;
            float w2 = S.dis[s2] * dn, w3 = S.dis[s3] * dn;
            a0.x = fmaf(w0, v0.x, a0.x);  a0.y = fmaf(w0, v0.y, a0.y);
            a1.x = fmaf(w1, v1.x, a1.x);  a1.y = fmaf(w1, v1.y, a1.y);
            a2.x = fmaf(w2, v2.x, a2.x);  a2.y = fmaf(w2, v2.y, a2.y);
            a3.x = fmaf(w3, v3.x, a3.x);  a3.y = fmaf(w3, v3.y, a3.y);
        }
        for (; k < ke; ++k) {
            int s = S.csr_src[k];
            float2 v0 = reinterpret_cast<const float2*>(xg + (size_t)s * F_)[lane];
            float w = S.dis[s] * dn;
            a0.x = fmaf(w, v0.x, a0.x);  a0.y = fmaf(w, v0.y, a0.y);
        }
        float ax = (a0.x + a1.x) + (a2.x + a3.x);
        float ay = (a0.y + a1.y) + (a2.y + a3.y);
        float v = warp_sum(fabsf(xc.x - ax) + fabsf(xc.y - ay));
        if (lane == 0) S.scorev[n] = v;
    }
    if (tid >= NPG) S.scorev[tid] = -3.4e38f;
    __syncthreads();

    // ====== Phase 2: hybrid bitonic sort on packed u64 (score desc, idx asc)
    unsigned long long key;
    {
        float sc = S.scorev[tid];
        unsigned sb  = __float_as_uint(sc);
        unsigned ord = (sb & 0x80000000u) ? ~sb : (sb | 0x80000000u);
        key = ((unsigned long long)ord << 32) | (unsigned)(~tid);
    }
    unsigned long long* kb64 = reinterpret_cast<unsigned long long*>(S.arena);

    #pragma unroll
    for (int k = 2; k <= 32; k <<= 1) {         // k = 2..32 in registers
        #pragma unroll
        for (int j = k >> 1; j > 0; j >>= 1) {
            unsigned long long pk = shfl_xor_u64(key, j);
            bool isLow   = ((lane & j) == 0);
            bool dirDesc = ((tid  & k) == 0);
            bool takeMax = (isLow == dirDesc);
            key = ((pk > key) == takeMax) ? pk : key;
        }
    }
    #pragma unroll
    for (int k = 64; k <= NTH; k <<= 1) {       // k = 64..512
        for (int j = k >> 1; j >= 32; j >>= 1) {
            kb64[tid] = key;
            __syncthreads();
            unsigned long long pk = kb64[tid ^ j];
            bool isLow   = ((tid & j) == 0);
            bool dirDesc = ((tid & k) == 0);
            bool takeMax = (isLow == dirDesc);
            key = ((pk > key) == takeMax) ? pk : key;
            __syncthreads();
        }
        #pragma unroll
        for (int j = 16; j > 0; j >>= 1) {
            unsigned long long pk = shfl_xor_u64(key, j);
            bool isLow   = ((lane & j) == 0);
            bool dirDesc = ((tid  & k) == 0);
            bool takeMax = (isLow == dirDesc);
            key = ((pk > key) == takeMax) ? pk : key;
        }
    }
    for (int n = tid; n < NPG; n += NTH) S.mapv[n] = -1;
    __syncthreads();
    if (tid < KPG) {
        int idx = (int)(~(unsigned)key) & (NTH - 1);
        S.klist[tid] = (unsigned short)idx;
        S.mapv[idx]  = (short)tid;
    }
    __syncthreads();

    // ====== Phase 3a: W1/b1 stage, in-place CSR compaction, d2 ==============
    {
        const float4* src = reinterpret_cast<const float4*>(W1);
        float4*       dst = reinterpret_cast<float4*>(&S.u2.mm.W1s[0][0]);
        for (int i = tid; i < F_ * F_ / 4; i += NTH) dst[i] = src[i];
    }
    if (tid < F_) S.u2.mm.b1s[tid] = b1[tid];
    const float beta = beta_p[0];

    if (tid < KPG) {
        int n = S.klist[tid];
        unsigned kb = n ? S.col_off[n - 1] : 0u;
        unsigned ke = S.col_off[n];
        unsigned w  = kb;
        for (unsigned k = kb; k < ke; ++k) {
            short m = S.mapv[S.csr_src[k]];
            if (m >= 0) S.csr_src[w++] = (unsigned short)m;
        }
        int cnt = (int)(w - kb);
        S.vcnt[tid] = (unsigned short)cnt;
        S.d2k[tid]  = 1.0f / sqrtf((float)(cnt + 1));
    }
    __syncthreads();

    // ====== Phase 3b: z-gather + matmul + fused norm/self-logit epilogue ====
    float2* HB2 = reinterpret_cast<float2*>(S.arena);
    const float2* W2 = reinterpret_cast<const float2*>(&S.u2.mm.W1s[0][0]);
    {
        float2 b2 = reinterpret_cast<const float2*>(S.u2.mm.b1s)[lane];
        for (int i0 = 2 * wid; i0 < KPG; i0 += 2 * NW) {
            #pragma unroll
            for (int r = 0; r < 2; ++r) {
                int i = i0 + r;
                if (i >= KPG) break;
                int n = S.klist[i];
                float d2c = S.d2k[i];
                const float2* xr = reinterpret_cast<const float2*>(xg + (size_t)n * F_);
                float2 xv = xr[lane];
                float  sf = d2c * d2c;
                float2 z  = make_float2(sf * xv.x, sf * xv.y);
                unsigned kb = n ? S.col_off[n - 1] : 0u;
                unsigned ke = kb + S.vcnt[i];
                for (unsigned k = kb; k < ke; ++k) {
                    int rs = S.csr_src[k];
                    float nm = S.d2k[rs] * d2c;
                    const float2* xj = reinterpret_cast<const float2*>(
                        xg + (size_t)S.klist[rs] * F_);
                    float2 xw = xj[lane];
                    z.x = fmaf(nm, xw.x, z.x);
                    z.y = fmaf(nm, xw.y, z.y);
                }
                reinterpret_cast<float2*>(S.u2.mm.zst[wid][r])[lane] = z;
            }
            __syncwarp();
            float2 a0 = b2, a1 = b2;
            #pragma unroll
            for (int k2 = 0; k2 < F_; ++k2) {
                float2 w = W2[k2 * 32 + lane];
                float z0 = S.u2.mm.zst[wid][0][k2];
                float z1 = S.u2.mm.zst[wid][1][k2];
                a0.x = fmaf(z0, w.x, a0.x);  a0.y = fmaf(z0, w.y, a0.y);
                a1.x = fmaf(z1, w.x, a1.x);  a1.y = fmaf(z1, w.y, a1.y);
            }
            a0.x = fmaxf(a0.x, 0.f);  a0.y = fmaxf(a0.y, 0.f);
            a1.x = fmaxf(a1.x, 0.f);  a1.y = fmaxf(a1.y, 0.f);
            HB2[i0 * 32 + lane] = a0;
            // fused P4a for row i0: norm + self logit (row in regs)
            {
                float ss = warp_sum(a0.x * a0.x + a0.y * a0.y);
                float ni = 1.0f / fmaxf(sqrtf(ss), 1e-12f);
                if (lane == 0) {
                    S.ninv[i0]   = ni;
                    S.scorev[i0] = beta * ss * ni * ni;
                }
            }
            if (i0 + 1 < KPG) {
                HB2[(i0 + 1) * 32 + lane] = a1;
                float ss = warp_sum(a1.x * a1.x + a1.y * a1.y);
                float ni = 1.0f / fmaxf(sqrtf(ss), 1e-12f);
                if (lane == 0) {
                    S.ninv[i0 + 1]   = ni;
                    S.scorev[i0 + 1] = beta * ss * ni * ni;
                }
            }
            __syncwarp();
        }
    }
    __syncthreads();

    // ====== Phase 4: AGNN chunk-4 online softmax + fused readout ============
    float2 msum = make_float2(0.f, 0.f);
    float2 mmax = make_float2(-3.4e38f, -3.4e38f);
    for (int i = wid; i < KPG; i += NW) {
        int n = S.klist[i];
        unsigned kb = n ? S.col_off[n - 1] : 0u;
        int dv = (int)S.vcnt[i];
        float ni = S.ninv[i];
        float2 hn = HB2[i * 32 + lane];
        float m     = S.scorev[i];                  // logit_s
        float denom = 1.0f;
        float2 acc  = hn;
        for (int c = 0; c < dv; c += 4) {
            int cnt = dv - c;  if (cnt > 4) cnt = 4;
            int   rs0, rs1, rs2, rs3;
            float d0, d1, d2, d3;
            rs0 = S.csr_src[kb + c];
            rs1 = (cnt > 1) ? (int)S.csr_src[kb + c + 1] : rs0;
            rs2 = (cnt > 2) ? (int)S.csr_src[kb + c + 2] : rs0;
            rs3 = (cnt > 3) ? (int)S.csr_src[kb + c + 3] : rs0;
            {
                float2 h0 = HB2[rs0 * 32 + lane];
                float2 h1 = HB2[rs1 * 32 + lane];
                float2 h2 = HB2[rs2 * 32 + lane];
                float2 h3 = HB2[rs3 * 32 + lane];
                d0 = fmaf(hn.x, h0.x, hn.y * h0.y);
                d1 = fmaf(hn.x, h1.x, hn.y * h1.y);
                d2 = fmaf(hn.x, h2.x, hn.y * h2.y);
                d3 = fmaf(hn.x, h3.x, hn.y * h3.y);
            }
            #pragma unroll
            for (int o = 16; o; o >>= 1) {          // 4 interleaved trees
                d0 += __shfl_xor_sync(0xffffffffu, d0, o);
                d1 += __shfl_xor_sync(0xffffffffu, d1, o);
                d2 += __shfl_xor_sync(0xffffffffu, d2, o);
                d3 += __shfl_xor_sync(0xffffffffu, d3, o);
            }
            d0 = beta * d0 * ni * S.ninv[rs0];
            d1 = (cnt > 1) ? beta * d1 * ni * S.ninv[rs1] : -3.4e38f;
            d2 = (cnt > 2) ? beta * d2 * ni * S.ninv[rs2] : -3.4e38f;
            d3 = (cnt > 3) ? beta * d3 * ni * S.ninv[rs3] : -3.4e38f;
            float cm = fmaxf(fmaxf(d0, d1), fmaxf(d2, d3));
            float mn = fmaxf(m, cm);
            float cr = __expf(m - mn);
            denom *= cr;
            acc.x *= cr;  acc.y *= cr;
            {
                float e0 = __expf(d0 - mn);
                float2 hs = HB2[rs0 * 32 + lane];
                denom += e0;
                acc.x = fmaf(e0, hs.x, acc.x);
                acc.y = fmaf(e0, hs.y, acc.y);
            }
            if (cnt > 1) {
                float e1 = __expf(d1 - mn);
                float2 hs = HB2[rs1 * 32 + lane];
                denom += e1;
                acc.x = fmaf(e1, hs.x, acc.x);
                acc.y = fmaf(e1, hs.y, acc.y);
            }
            if (cnt > 2) {
                float e2 = __expf(d2 - mn);
                float2 hs = HB2[rs2 * 32 + lane];
                denom += e2;
                acc.x = fmaf(e2, hs.x, acc.x);
                acc.y = fmaf(e2, hs.y, acc.y);
            }
            if (cnt > 3) {
                float e3 = __expf(d3 - mn);
                float2 hs = HB2[rs3 * 32 + lane];
                denom += e3;
                acc.x = fmaf(e3, hs.x, acc.x);
                acc.y = fmaf(e3, hs.y, acc.y);
            }
            m = mn;
        }
        float inv = 1.0f / denom;
        float2 o = make_float2(acc.x * inv, acc.y * inv);
        msum.x += o.x;  msum.y += o.y;
        mmax.x = fmaxf(mmax.x, o.x);
        mmax.y = fmaxf(mmax.y, o.y);
    }
    __syncthreads();                                 // csr_src now dead
    {
        float* RS = reinterpret_cast<float*>(S.csr_src);        // [16][64]
        float* RM = RS + NW * F_;                               // [16][64]
        reinterpret_cast<float2*>(RS)[wid * 32 + lane] = msum;
        reinterpret_cast<float2*>(RM)[wid * 32 + lane] = mmax;
        __syncthreads();
        if (tid < F_) {
            float s = 0.f;
            #pragma unroll
            for (int w = 0; w < NW; ++w) s += RS[w * F_ + tid];
            out[(size_t)g * (2 * F_) + tid] = fmaxf(s * (1.0f / (float)KPG), 0.f);
        } else if (tid < 2 * F_) {
            int f = tid - F_;
            float m2 = -3.4e38f;
            #pragma unroll
            for (int w = 0; w < NW; ++w) m2 = fmaxf(m2, RM[w * F_ + f]);
            out[(size_t)g * (2 * F_) + F_ + f] = fmaxf(m2, 0.f);
        }
    }
}

extern "C" void kernel_launch(void* const* d_in, const int* in_sizes, int n_in,
                              void* d_out, int out_size)
{
    const float* x    = (const float*)d_in[0];
    const int*   ei   = (const int*)  d_in[1];
    const float* W1   = (const float*)d_in[2];
    const float* b1   = (const float*)d_in[3];
    const float* beta = (const float*)d_in[4];
    float*       out  = (float*)d_out;

    int smem = (int)sizeof(SmemLayout);
    cudaFuncSetAttribute(gp_fused_kernel,
                         cudaFuncAttributeMaxDynamicSharedMemorySize, smem);
    gp_fused_kernel<<<G_, NTH, smem>>>(x, ei, W1, b1, beta, out);
}